// round 3
// baseline (speedup 1.0000x reference)
#include <cuda_runtime.h>

#define BATCH 16384
#define CH    30
#define GG    49            // 7*7 cells per image
#define IMG   4             // images per block
#define TPB   224           // 7 warps; 196 compute threads (4*49)
#define NBLK  (BATCH / IMG) // 4096
#define FPI   1470          // floats per image (30*49)
#define F4PB  ((IMG * FPI) / 4)  // 1470 float4 per tensor per block

__device__ double g_partials[NBLK];

__global__ void __launch_bounds__(TPB)
yolo_main_kernel(const float* __restrict__ pred, const float* __restrict__ labels) {
    __shared__ float sp[IMG * FPI];
    __shared__ float sl[IMG * FPI];
    __shared__ double sdata[TPB / 32];

    const int t  = threadIdx.x;
    const size_t base = (size_t)blockIdx.x * (IMG * FPI);

    // ---- Phase 1: bulk coalesced float4 staging (fully unrolled, predicated) ----
    const float4* gp = (const float4*)(pred + base);
    const float4* gl = (const float4*)(labels + base);
    float4* s4p = (float4*)sp;
    float4* s4l = (float4*)sl;
    #pragma unroll
    for (int k = 0; k < 7; k++) {               // 7*224 = 1568 >= 1470
        int i = t + k * TPB;
        if (i < F4PB) {
            s4p[i] = gp[i];
            s4l[i] = gl[i];
        }
    }
    __syncthreads();

    // ---- Phase 2: per-cell loss from smem ----
    double val = 0.0;
    if (t < IMG * GG) {
        int img  = t / GG;
        int cell = t - img * GG;
        int m    = cell / 7;      // dim -2 index -> gx
        int n    = cell - m * 7;  // dim -1 index -> gy

        const float* pb = sp + img * FPI + cell;
        const float* lb = sl + img * FPI + cell;

        float p0 = pb[0*GG], p1 = pb[1*GG], p2 = pb[2*GG], p3 = pb[3*GG], p4 = pb[4*GG];
        float p5 = pb[5*GG], p6 = pb[6*GG], p7 = pb[7*GG], p8 = pb[8*GG], p9 = pb[9*GG];
        float l0 = lb[0*GG], l1 = lb[1*GG], l2 = lb[2*GG], l3 = lb[3*GG], l4 = lb[4*GG];
        float l5 = lb[5*GG], l6 = lb[6*GG], l7 = lb[7*GG], l8 = lb[8*GG];

        float gx = (float)m, gy = (float)n;
        const float inv = 1.0f / 7.0f;

        // box 1 (pred ch 0..3)
        float cx1 = (p0 + gx) * inv, cy1 = (p1 + gy) * inv;
        float a1x1 = cx1 - p2 * 0.5f, a1y1 = cy1 - p3 * 0.5f;
        float a1x2 = cx1 + p2 * 0.5f, a1y2 = cy1 + p3 * 0.5f;
        // box 2 (pred ch 5..8)
        float cx2 = (p5 + gx) * inv, cy2 = (p6 + gy) * inv;
        float a2x1 = cx2 - p7 * 0.5f, a2y1 = cy2 - p8 * 0.5f;
        float a2x2 = cx2 + p7 * 0.5f, a2y2 = cy2 + p8 * 0.5f;
        // gt box (labels ch 0..3)
        float cxg = (l0 + gx) * inv, cyg = (l1 + gy) * inv;
        float bx1 = cxg - l2 * 0.5f, by1 = cyg - l3 * 0.5f;
        float bx2 = cxg + l2 * 0.5f, by2 = cyg + l3 * 0.5f;

        float areaB = (bx2 - bx1) * (by2 - by1);

        // iou1
        float ix1 = fmaxf(a1x1, bx1), iy1 = fmaxf(a1y1, by1);
        float ix2 = fminf(a1x2, bx2), iy2 = fminf(a1y2, by2);
        float inter1 = fmaxf(ix2 - ix1, 0.0f) * fmaxf(iy2 - iy1, 0.0f);
        float areaA1 = (a1x2 - a1x1) * (a1y2 - a1y1);
        float iou1 = (inter1 > 0.0f) ? inter1 / (areaA1 + areaB - inter1) : 0.0f;

        // iou2
        float jx1 = fmaxf(a2x1, bx1), jy1 = fmaxf(a2y1, by1);
        float jx2 = fminf(a2x2, bx2), jy2 = fminf(a2y2, by2);
        float inter2 = fmaxf(jx2 - jx1, 0.0f) * fmaxf(jy2 - jy1, 0.0f);
        float areaA2 = (a2x2 - a2x1) * (a2y2 - a2y1);
        float iou2 = (inter2 > 0.0f) ? inter2 / (areaA2 + areaB - inter2) : 0.0f;

        bool resp1 = iou1 > iou2;
        float obj = (l4 == 1.0f) ? 1.0f : 0.0f;

        float d0 = p0 - l0, d1 = p1 - l1;
        float s2 = sqrtf(p2) - sqrtf(l2), s3 = sqrtf(p3) - sqrtf(l3);
        float coor1 = d0*d0 + d1*d1 + s2*s2 + s3*s3;
        float e0 = p5 - l5, e1 = p6 - l6;
        float t2 = sqrtf(p7) - sqrtf(l7), t3 = sqrtf(p8) - sqrtf(l8);
        float coor2 = e0*e0 + e1*e1 + t2*t2 + t3*t3;
        float coor = resp1 ? coor1 : coor2;

        float d4 = p4 - iou1, d9 = p9 - iou2;
        float q4 = d4 * d4, q9 = d9 * d9;
        float obj_conf   = resp1 ? q4 : q9;
        float noobj_resp = resp1 ? q9 : q4;

        // class loss: ch 10..29
        float cls = 0.0f;
        #pragma unroll
        for (int c = 10; c < 30; c++) {
            float dc = pb[c * GG] - lb[c * GG];
            cls += dc * dc;
        }

        float contrib = obj * (5.0f * coor + obj_conf + 0.5f * noobj_resp + cls)
                      + (1.0f - obj) * 0.5f * (p4 * p4 + p9 * p9);
        val = (double)contrib;
    }

    // ---- Phase 3: deterministic block reduction (double) ----
    #pragma unroll
    for (int o = 16; o > 0; o >>= 1)
        val += __shfl_down_sync(0xffffffffu, val, o);

    int lane = t & 31;
    int wid  = t >> 5;
    if (lane == 0) sdata[wid] = val;
    __syncthreads();
    if (wid == 0) {
        val = (lane < TPB / 32) ? sdata[lane] : 0.0;
        #pragma unroll
        for (int o = 4; o > 0; o >>= 1)
            val += __shfl_down_sync(0xffffffffu, val, o);
        if (lane == 0) g_partials[blockIdx.x] = val;
    }
}

__global__ void __launch_bounds__(1024)
yolo_final_kernel(float* __restrict__ out) {
    double val = 0.0;
    #pragma unroll
    for (int k = 0; k < NBLK / 1024; k++)
        val += g_partials[threadIdx.x + k * 1024];

    #pragma unroll
    for (int o = 16; o > 0; o >>= 1)
        val += __shfl_down_sync(0xffffffffu, val, o);

    __shared__ double sdata[32];
    int lane = threadIdx.x & 31;
    int wid  = threadIdx.x >> 5;
    if (lane == 0) sdata[wid] = val;
    __syncthreads();
    if (wid == 0) {
        val = sdata[lane];
        #pragma unroll
        for (int o = 16; o > 0; o >>= 1)
            val += __shfl_down_sync(0xffffffffu, val, o);
        if (lane == 0) out[0] = (float)(val / 6.0);
    }
}

extern "C" void kernel_launch(void* const* d_in, const int* in_sizes, int n_in,
                              void* d_out, int out_size) {
    const float* pred   = (const float*)d_in[0];
    const float* labels = (const float*)d_in[1];
    float* out = (float*)d_out;

    yolo_main_kernel<<<NBLK, TPB>>>(pred, labels);
    yolo_final_kernel<<<1, 1024>>>(out);
}

// round 4
// speedup vs baseline: 1.0777x; 1.0777x over previous
#include <cuda_runtime.h>

#define BATCH 16384
#define CH    30
#define GG    49             // 7*7 cells per image
#define CELLS (BATCH * GG)   // 802816
#define TPB   256
#define CPT   2              // cells per thread
#define NBLK  (CELLS / (TPB * CPT))  // 1568, exact

__device__ double g_partials[NBLK];
__device__ unsigned int g_count = 0;  // atom.inc wraps to 0 each run -> graph-replay safe

__device__ __forceinline__ float cell_loss(const float* __restrict__ pred,
                                           const float* __restrict__ labels,
                                           int tid) {
    int b    = tid / GG;
    int cell = tid - b * GG;
    int m    = cell / 7;      // dim -2 index -> gx
    int n    = cell - m * 7;  // dim -1 index -> gy

    const float* pb = pred   + (size_t)b * (CH * GG) + cell;
    const float* lb = labels + (size_t)b * (CH * GG) + cell;

    float p0 = pb[0*GG], p1 = pb[1*GG], p2 = pb[2*GG], p3 = pb[3*GG], p4 = pb[4*GG];
    float p5 = pb[5*GG], p6 = pb[6*GG], p7 = pb[7*GG], p8 = pb[8*GG], p9 = pb[9*GG];
    float l0 = lb[0*GG], l1 = lb[1*GG], l2 = lb[2*GG], l3 = lb[3*GG], l4 = lb[4*GG];
    float l5 = lb[5*GG], l6 = lb[6*GG], l7 = lb[7*GG], l8 = lb[8*GG];

    float gx = (float)m, gy = (float)n;
    const float inv = 1.0f / 7.0f;

    // box 1 (pred ch 0..3)
    float cx1 = (p0 + gx) * inv, cy1 = (p1 + gy) * inv;
    float a1x1 = cx1 - p2 * 0.5f, a1y1 = cy1 - p3 * 0.5f;
    float a1x2 = cx1 + p2 * 0.5f, a1y2 = cy1 + p3 * 0.5f;
    // box 2 (pred ch 5..8)
    float cx2 = (p5 + gx) * inv, cy2 = (p6 + gy) * inv;
    float a2x1 = cx2 - p7 * 0.5f, a2y1 = cy2 - p8 * 0.5f;
    float a2x2 = cx2 + p7 * 0.5f, a2y2 = cy2 + p8 * 0.5f;
    // gt box (labels ch 0..3)
    float cxg = (l0 + gx) * inv, cyg = (l1 + gy) * inv;
    float bx1 = cxg - l2 * 0.5f, by1 = cyg - l3 * 0.5f;
    float bx2 = cxg + l2 * 0.5f, by2 = cyg + l3 * 0.5f;

    float areaB = (bx2 - bx1) * (by2 - by1);

    // iou1
    float ix1 = fmaxf(a1x1, bx1), iy1 = fmaxf(a1y1, by1);
    float ix2 = fminf(a1x2, bx2), iy2 = fminf(a1y2, by2);
    float inter1 = fmaxf(ix2 - ix1, 0.0f) * fmaxf(iy2 - iy1, 0.0f);
    float areaA1 = (a1x2 - a1x1) * (a1y2 - a1y1);
    float iou1 = (inter1 > 0.0f) ? inter1 / (areaA1 + areaB - inter1) : 0.0f;

    // iou2
    float jx1 = fmaxf(a2x1, bx1), jy1 = fmaxf(a2y1, by1);
    float jx2 = fminf(a2x2, bx2), jy2 = fminf(a2y2, by2);
    float inter2 = fmaxf(jx2 - jx1, 0.0f) * fmaxf(jy2 - jy1, 0.0f);
    float areaA2 = (a2x2 - a2x1) * (a2y2 - a2y1);
    float iou2 = (inter2 > 0.0f) ? inter2 / (areaA2 + areaB - inter2) : 0.0f;

    bool resp1 = iou1 > iou2;
    float obj = (l4 == 1.0f) ? 1.0f : 0.0f;

    float d0 = p0 - l0, d1 = p1 - l1;
    float s2 = sqrtf(p2) - sqrtf(l2), s3 = sqrtf(p3) - sqrtf(l3);
    float coor1 = d0*d0 + d1*d1 + s2*s2 + s3*s3;
    float e0 = p5 - l5, e1 = p6 - l6;
    float t2 = sqrtf(p7) - sqrtf(l7), t3 = sqrtf(p8) - sqrtf(l8);
    float coor2 = e0*e0 + e1*e1 + t2*t2 + t3*t3;
    float coor = resp1 ? coor1 : coor2;

    float d4 = p4 - iou1, d9 = p9 - iou2;
    float q4 = d4 * d4, q9 = d9 * d9;
    float obj_conf   = resp1 ? q4 : q9;
    float noobj_resp = resp1 ? q9 : q4;

    // class loss: ch 10..29
    float cls = 0.0f;
    #pragma unroll
    for (int c = 10; c < 30; c++) {
        float dc = pb[c * GG] - lb[c * GG];
        cls += dc * dc;
    }

    return obj * (5.0f * coor + obj_conf + 0.5f * noobj_resp + cls)
         + (1.0f - obj) * 0.5f * (p4 * p4 + p9 * p9);
}

__global__ void __launch_bounds__(TPB)
yolo_fused_kernel(const float* __restrict__ pred, const float* __restrict__ labels,
                  float* __restrict__ out) {
    __shared__ double sdata[TPB / 32];
    __shared__ bool is_last;

    const int t = threadIdx.x;
    int i0 = blockIdx.x * (TPB * CPT) + t;   // block covers a contiguous 512-cell span

    double val = (double)cell_loss(pred, labels, i0)
               + (double)cell_loss(pred, labels, i0 + TPB);

    // deterministic block reduction (double)
    #pragma unroll
    for (int o = 16; o > 0; o >>= 1)
        val += __shfl_down_sync(0xffffffffu, val, o);

    int lane = t & 31;
    int wid  = t >> 5;
    if (lane == 0) sdata[wid] = val;
    __syncthreads();
    if (wid == 0) {
        val = (lane < TPB / 32) ? sdata[lane] : 0.0;
        #pragma unroll
        for (int o = 4; o > 0; o >>= 1)
            val += __shfl_down_sync(0xffffffffu, val, o);
        if (lane == 0) {
            g_partials[blockIdx.x] = val;          // plain store (L2 via release below)
            unsigned prev;
            // release: orders the partial store to gpu scope BEFORE the counter bump;
            // avoids __threadfence()'s CCTL.IVALL full-L1 flush. Wraps at NBLK-1 -> 0.
            asm volatile("atom.release.gpu.global.inc.u32 %0, [%1], %2;"
                         : "=r"(prev)
                         : "l"(&g_count), "r"((unsigned)(NBLK - 1))
                         : "memory");
            is_last = (prev == NBLK - 1);
        }
    }
    __syncthreads();

    if (is_last) {
        // last-arriving block: deterministic final reduction.
        // acquire loads go to L2 (never stale L1 lines) and pair with producers' releases.
        double acc = 0.0;
        #pragma unroll
        for (int k = 0; k < NBLK / TPB; k++) {   // 1568/256 = 6.125 -> 6 full + tail
            double v;
            const double* p = &g_partials[t + k * TPB];
            asm volatile("ld.global.acquire.gpu.f64 %0, [%1];" : "=d"(v) : "l"(p) : "memory");
            acc += v;
        }
        {
            int i = t + (NBLK / TPB) * TPB;
            if (i < NBLK) {
                double v;
                const double* p = &g_partials[i];
                asm volatile("ld.global.acquire.gpu.f64 %0, [%1];" : "=d"(v) : "l"(p) : "memory");
                acc += v;
            }
        }
        #pragma unroll
        for (int o = 16; o > 0; o >>= 1)
            acc += __shfl_down_sync(0xffffffffu, acc, o);
        if (lane == 0) sdata[wid] = acc;
        __syncthreads();
        if (wid == 0) {
            acc = (lane < TPB / 32) ? sdata[lane] : 0.0;
            #pragma unroll
            for (int o = 4; o > 0; o >>= 1)
                acc += __shfl_down_sync(0xffffffffu, acc, o);
            if (lane == 0) out[0] = (float)(acc / 6.0);
        }
    }
}

extern "C" void kernel_launch(void* const* d_in, const int* in_sizes, int n_in,
                              void* d_out, int out_size) {
    const float* pred   = (const float*)d_in[0];
    const float* labels = (const float*)d_in[1];
    float* out = (float*)d_out;

    yolo_fused_kernel<<<NBLK, TPB>>>(pred, labels, out);
}